// round 1
// baseline (speedup 1.0000x reference)
#include <cuda_runtime.h>
#include <math.h>

#define SEQ    2048
#define HEADS  16
#define HD     64
#define EMB    1024
#define BATCH  4
#define ROWS   (BATCH * SEQ)   // 8192
#define SCALE  0.125f
#define MASKP  (-50.0f)

// Scratch (allocation-free rule: __device__ globals)
__device__ float g_q[ROWS * EMB];
__device__ float g_k[ROWS * EMB];
__device__ float g_v[ROWS * EMB];
__device__ float g_a[ROWS * EMB];

// ---------------------------------------------------------------------------
// 128x128x8 fp32 GEMM, 256 threads, 8x8 microtile. C[M,N] = A[M,K] @ B[K,N].
// M,N,K all multiples of 128/128/8 here (8192/1024/1024) -> no bounds checks.
// ---------------------------------------------------------------------------
__global__ __launch_bounds__(256) void sgemm_128x128(
    const float* __restrict__ A, const float* __restrict__ B,
    float* __restrict__ C, int M, int N, int K)
{
    __shared__ float As[8][128];   // transposed: As[k][m]
    __shared__ float Bs[8][128];   // Bs[k][n]

    const int tid = threadIdx.x;
    const int tx  = tid & 15;      // 0..15  -> n microtile
    const int ty  = tid >> 4;      // 0..15  -> m microtile
    const int bm  = blockIdx.y * 128;
    const int bn  = blockIdx.x * 128;

    // A-tile load mapping: one float4 per thread (128 rows x 8 k = 256 float4)
    const int am = tid >> 1;            // 0..127
    const int ak = (tid & 1) * 4;       // 0 or 4
    // B-tile load mapping: one float4 per thread (8 rows x 128 n = 256 float4)
    const int br = tid >> 5;            // 0..7
    const int bc = (tid & 31) * 4;      // 0..124

    const float* Ap = A + (size_t)(bm + am) * K + ak;
    const float* Bp = B + (size_t)br * N + bn + bc;

    float acc[8][8];
    #pragma unroll
    for (int i = 0; i < 8; ++i)
        #pragma unroll
        for (int j = 0; j < 8; ++j) acc[i][j] = 0.0f;

    for (int kb = 0; kb < K; kb += 8) {
        float4 a4 = *(const float4*)(Ap + kb);
        float4 b4 = *(const float4*)(Bp + (size_t)kb * N);
        As[ak + 0][am] = a4.x;
        As[ak + 1][am] = a4.y;
        As[ak + 2][am] = a4.z;
        As[ak + 3][am] = a4.w;
        *(float4*)&Bs[br][bc] = b4;
        __syncthreads();

        #pragma unroll
        for (int k = 0; k < 8; ++k) {
            float a[8], b[8];
            #pragma unroll
            for (int i = 0; i < 8; ++i) a[i] = As[k][ty * 8 + i];
            #pragma unroll
            for (int j = 0; j < 8; ++j) b[j] = Bs[k][tx * 8 + j];
            #pragma unroll
            for (int i = 0; i < 8; ++i)
                #pragma unroll
                for (int j = 0; j < 8; ++j)
                    acc[i][j] += a[i] * b[j];
        }
        __syncthreads();
    }

    #pragma unroll
    for (int i = 0; i < 8; ++i) {
        float* Cp = C + (size_t)(bm + ty * 8 + i) * N + bn + tx * 8;
        #pragma unroll
        for (int j = 0; j < 8; ++j) Cp[j] = acc[i][j];
    }
}

// ---------------------------------------------------------------------------
// Attention: one CTA handles 64 query rows of one (b, h). Streams K/V in
// 64-row tiles. Scores are small (std ~0.4) so softmax without max-shift is
// numerically exact in fp32: accumulate unnormalized O and row sums, divide
// at the end. Layout of q/k/v/a: [b, s, h*64 + d] == row (b*S+s) of [ROWS,EMB].
// ---------------------------------------------------------------------------
__global__ __launch_bounds__(256) void attn_kernel(
    const float* __restrict__ Q, const float* __restrict__ K,
    const float* __restrict__ V, float* __restrict__ O)
{
    extern __shared__ float sm[];
    float* Qs = sm;                // [64][65]
    float* Ks = sm + 64 * 65;      // [64][65]
    float* Vs = sm + 2 * 64 * 65;  // [64][65]
    float* Ps = sm + 3 * 64 * 65;  // [64][65]
    float* rs = sm + 4 * 64 * 65;  // [64] running row sums

    const int tid = threadIdx.x;
    const int tx  = tid & 15;
    const int ty  = tid >> 4;
    const int q0  = blockIdx.x * 64;
    const int h   = blockIdx.y;
    const int b   = blockIdx.z;

    const size_t slice = (size_t)b * SEQ * EMB + (size_t)h * HD;  // (b,*,h,0)
    const float* Qg = Q + slice;
    const float* Kg = K + slice;
    const float* Vg = V + slice;
    float*       Og = O + slice;

    // Load Q tile
    for (int i = tid; i < 64 * 64; i += 256) {
        int r = i >> 6, d = i & 63;
        Qs[r * 65 + d] = Qg[(size_t)(q0 + r) * EMB + d];
    }
    if (tid < 64) rs[tid] = 0.0f;

    float o[4][4];
    #pragma unroll
    for (int i = 0; i < 4; ++i)
        #pragma unroll
        for (int j = 0; j < 4; ++j) o[i][j] = 0.0f;

    for (int k0 = 0; k0 < SEQ; k0 += 64) {
        __syncthreads();  // prior iter's Ps/Vs consumers done (also covers rs init)
        for (int i = tid; i < 64 * 64; i += 256) {
            int r = i >> 6, d = i & 63;
            Ks[r * 65 + d] = Kg[(size_t)(k0 + r) * EMB + d];
            Vs[r * 65 + d] = Vg[(size_t)(k0 + r) * EMB + d];
        }
        __syncthreads();

        // S = Q K^T for this 64x64 tile
        float s[4][4];
        #pragma unroll
        for (int i = 0; i < 4; ++i)
            #pragma unroll
            for (int j = 0; j < 4; ++j) s[i][j] = 0.0f;

        for (int d = 0; d < 64; ++d) {
            float qa[4], kb_[4];
            #pragma unroll
            for (int i = 0; i < 4; ++i) qa[i]  = Qs[(ty * 4 + i) * 65 + d];
            #pragma unroll
            for (int j = 0; j < 4; ++j) kb_[j] = Ks[(tx * 4 + j) * 65 + d];
            #pragma unroll
            for (int i = 0; i < 4; ++i)
                #pragma unroll
                for (int j = 0; j < 4; ++j)
                    s[i][j] += qa[i] * kb_[j];
        }

        // scale + causal(-50) + exp -> P in smem
        #pragma unroll
        for (int i = 0; i < 4; ++i) {
            int qr = q0 + ty * 4 + i;
            #pragma unroll
            for (int j = 0; j < 4; ++j) {
                int kc = k0 + tx * 4 + j;
                float val = s[i][j] * SCALE + (kc > qr ? MASKP : 0.0f);
                Ps[(ty * 4 + i) * 65 + (tx * 4 + j)] = __expf(val);
            }
        }
        __syncthreads();

        // row sums (threads 0..63), concurrent with PV below (no conflict)
        if (tid < 64) {
            float sum = 0.0f;
            #pragma unroll 8
            for (int c = 0; c < 64; ++c) sum += Ps[tid * 65 + c];
            rs[tid] += sum;
        }

        // O += P @ V
        for (int c = 0; c < 64; ++c) {
            float pv[4], vv[4];
            #pragma unroll
            for (int i = 0; i < 4; ++i) pv[i] = Ps[(ty * 4 + i) * 65 + c];
            #pragma unroll
            for (int j = 0; j < 4; ++j) vv[j] = Vs[c * 65 + tx * 4 + j];
            #pragma unroll
            for (int i = 0; i < 4; ++i)
                #pragma unroll
                for (int j = 0; j < 4; ++j)
                    o[i][j] += pv[i] * vv[j];
        }
    }
    __syncthreads();  // rs final

    #pragma unroll
    for (int i = 0; i < 4; ++i) {
        float inv = 1.0f / rs[ty * 4 + i];
        #pragma unroll
        for (int j = 0; j < 4; ++j)
            Og[(size_t)(q0 + ty * 4 + i) * EMB + tx * 4 + j] = o[i][j] * inv;
    }
}

// ---------------------------------------------------------------------------
extern "C" void kernel_launch(void* const* d_in, const int* in_sizes, int n_in,
                              void* d_out, int out_size)
{
    const float* x  = (const float*)d_in[0];
    const float* Wq = (const float*)d_in[1];
    const float* Wk = (const float*)d_in[2];
    const float* Wv = (const float*)d_in[3];
    const float* Wr = (const float*)d_in[4];

    float *q, *k, *v, *a;
    cudaGetSymbolAddress((void**)&q, g_q);
    cudaGetSymbolAddress((void**)&k, g_k);
    cudaGetSymbolAddress((void**)&v, g_v);
    cudaGetSymbolAddress((void**)&a, g_a);

    const int attn_smem = (4 * 64 * 65 + 64) * (int)sizeof(float);  // 66,816 B
    cudaFuncSetAttribute(attn_kernel,
                         cudaFuncAttributeMaxDynamicSharedMemorySize, attn_smem);

    dim3 gemm_grid(EMB / 128, ROWS / 128);  // (8, 64)

    sgemm_128x128<<<gemm_grid, 256>>>(x, Wq, q, ROWS, EMB, EMB);
    sgemm_128x128<<<gemm_grid, 256>>>(x, Wk, k, ROWS, EMB, EMB);
    sgemm_128x128<<<gemm_grid, 256>>>(x, Wv, v, ROWS, EMB, EMB);

    attn_kernel<<<dim3(SEQ / 64, HEADS, BATCH), 256, attn_smem>>>(q, k, v, a);

    sgemm_128x128<<<gemm_grid, 256>>>(a, Wr, (float*)d_out, ROWS, EMB, EMB);
}